// round 1
// baseline (speedup 1.0000x reference)
#include <cuda_runtime.h>

#define BB 4
#define NN 512
#define DD 128
#define TAU_INV 2.0f
#define EPSF 1e-9f

// ---------------- scratch (__device__ globals; no allocation allowed) ----------------
__device__ float g_A  [NN * NN];        // softmax(A) (single copy)
__device__ float g_sj [BB * NN * DD];   // j-side: ES @ (Wp@W1_src) + bp@W1_src
__device__ float g_ti [BB * NN * DD];   // i-side: ES @ (Wp@W1_tgt) + bp@W1_tgt + b1
__device__ float g_Wcs[DD * DD];        // Wp @ W1_src
__device__ float g_Wct[DD * DD];        // Wp @ W1_tgt
__device__ float g_Bs [DD];
__device__ float g_Bt [DD];

// ---------------- K0: combine weights: Wc = Wp @ W1_{src,tgt}, biases ----------------
__global__ void k_combine(const float* __restrict__ Wp, const float* __restrict__ W1,
                          const float* __restrict__ bp, const float* __restrict__ b1)
{
    int m = threadIdx.x;            // 0..127
    int d = blockIdx.x;             // 0..128 (last block does biases)
    if (d < DD) {
        __shared__ float wp[DD];
        wp[m] = Wp[d * DD + m];
        __syncthreads();
        float as = 0.f, at = 0.f;
        #pragma unroll 4
        for (int k = 0; k < DD; k++) {
            float w = wp[k];
            as += w * W1[k * DD + m];
            at += w * W1[(k + DD) * DD + m];
        }
        g_Wcs[d * DD + m] = as;
        g_Wct[d * DD + m] = at;
    } else {
        float bs = 0.f, bt = 0.f;
        for (int k = 0; k < DD; k++) {
            float bv = bp[k];
            bs += bv * W1[k * DD + m];
            bt += bv * W1[(k + DD) * DD + m];
        }
        g_Bs[m] = bs;
        g_Bt[m] = bt + b1[m];   // fold b1 into the i-side term
    }
}

// ---------------- K1: Gumbel-softmax rows of (N,N); write A + 4 broadcast copies ------
__global__ void k_softmax(const float* __restrict__ logits, const float* __restrict__ u,
                          float* __restrict__ outA)
{
    int i = blockIdx.x;
    int j = threadIdx.x;            // 0..511
    int idx = i * NN + j;

    float g = -logf(-logf(u[idx] + EPSF) + EPSF);
    float x = (logits[idx] + g) * TAU_INV;

    __shared__ float red[16];
    // max reduce
    float m = x;
    #pragma unroll
    for (int o = 16; o > 0; o >>= 1) m = fmaxf(m, __shfl_xor_sync(0xffffffffu, m, o));
    if ((j & 31) == 0) red[j >> 5] = m;
    __syncthreads();
    float mx = red[0];
    #pragma unroll
    for (int w = 1; w < 16; w++) mx = fmaxf(mx, red[w]);
    __syncthreads();

    float ex = expf(x - mx);
    // sum reduce
    float s = ex;
    #pragma unroll
    for (int o = 16; o > 0; o >>= 1) s += __shfl_xor_sync(0xffffffffu, s, o);
    if ((j & 31) == 0) red[j >> 5] = s;
    __syncthreads();
    float ssum = red[0];
    #pragma unroll
    for (int w = 1; w < 16; w++) ssum += red[w];

    float a = ex / ssum;
    g_A[idx] = a;
    #pragma unroll
    for (int b = 0; b < BB; b++) outA[b * NN * NN + idx] = a;
}

// ---------------- K2: s,t = ES @ Wc_{s,t} + bias (rows tiled by 8) --------------------
#define RT 8
__global__ void __launch_bounds__(128) k_proj(const float* __restrict__ ES)
{
    __shared__ float es[RT][DD];
    int m  = threadIdx.x;           // 0..127
    int r0 = blockIdx.x * RT;       // flat row in [0, B*N)

    const float4* src = (const float4*)(ES + (size_t)r0 * DD);
    float4* dst = (float4*)(&es[0][0]);
    #pragma unroll
    for (int t = 0; t < (RT * DD / 4) / 128; t++) dst[m + t * 128] = src[m + t * 128];
    __syncthreads();

    float accS[RT], accT[RT];
    #pragma unroll
    for (int r = 0; r < RT; r++) { accS[r] = 0.f; accT[r] = 0.f; }

    #pragma unroll 2
    for (int d = 0; d < DD; d++) {
        float ws = g_Wcs[d * DD + m];
        float wt = g_Wct[d * DD + m];
        #pragma unroll
        for (int r = 0; r < RT; r++) {
            float e = es[r][d];
            accS[r] += e * ws;
            accT[r] += e * wt;
        }
    }
    float bs = g_Bs[m], bt = g_Bt[m];
    #pragma unroll
    for (int r = 0; r < RT; r++) {
        g_sj[(size_t)(r0 + r) * DD + m] = accS[r] + bs;
        g_ti[(size_t)(r0 + r) * DD + m] = accT[r] + bt;
    }
}

// ---------------- K3: v = Σ_j A[i,j] relu(t_i + s_j); out = ES + v@W2 + b2 ------------
#define TI 8      // i's per block
#define TJ 32     // j's per shared tile
__global__ void __launch_bounds__(256) k_main(const float* __restrict__ ES,
                                              const float* __restrict__ W2,
                                              const float* __restrict__ b2,
                                              float* __restrict__ out)
{
    __shared__ float sh_s[TJ][DD];   // 16 KB
    __shared__ float sh_a[TI][TJ];   // 1 KB
    __shared__ float sh_v[TI][DD];   // 4 KB

    int tid = threadIdx.x;
    int b   = blockIdx.y;
    int i0  = blockIdx.x * TI;
    int kp  = tid & 63;              // k-pair index (2 floats per thread)
    int ig  = tid >> 6;              // 0..3, each handles 2 i's

    float t0x, t0y, t1x, t1y;        // fixed i-side values (b1 folded in)
    {
        const float* p0 = &g_ti[((size_t)(b * NN + i0 + ig * 2 + 0)) * DD + kp * 2];
        const float* p1 = &g_ti[((size_t)(b * NN + i0 + ig * 2 + 1)) * DD + kp * 2];
        float2 v0 = *(const float2*)p0;  t0x = v0.x; t0y = v0.y;
        float2 v1 = *(const float2*)p1;  t1x = v1.x; t1y = v1.y;
    }
    float a0x = 0.f, a0y = 0.f, a1x = 0.f, a1y = 0.f;   // accumulators

    const float* sbase = g_sj + (size_t)b * NN * DD;

    for (int jc = 0; jc < NN; jc += TJ) {
        // load s tile (contiguous TJ*D floats)
        const float4* src = (const float4*)(sbase + (size_t)jc * DD);
        float4* dst = (float4*)(&sh_s[0][0]);
        #pragma unroll
        for (int t = 0; t < (TJ * DD / 4) / 256; t++) dst[tid + t * 256] = src[tid + t * 256];
        // load A tile (TI x TJ = 256 entries, one per thread)
        {
            int r = tid >> 5, c = tid & 31;
            sh_a[r][c] = g_A[(size_t)(i0 + r) * NN + jc + c];
        }
        __syncthreads();

        #pragma unroll 4
        for (int j = 0; j < TJ; j++) {
            float2 sv = *(const float2*)&sh_s[j][kp * 2];
            float aA = sh_a[ig * 2 + 0][j];
            float aB = sh_a[ig * 2 + 1][j];

            float x0, x1, y0, y1;
            // x = sv + t0  (packed add)
            asm("{\n\t.reg .b64 ra, rb, rc;\n\t"
                "mov.b64 ra, {%2, %3};\n\t"
                "mov.b64 rb, {%4, %5};\n\t"
                "add.rn.f32x2 rc, ra, rb;\n\t"
                "mov.b64 {%0, %1}, rc;\n\t}"
                : "=f"(x0), "=f"(x1) : "f"(sv.x), "f"(sv.y), "f"(t0x), "f"(t0y));
            asm("{\n\t.reg .b64 ra, rb, rc;\n\t"
                "mov.b64 ra, {%2, %3};\n\t"
                "mov.b64 rb, {%4, %5};\n\t"
                "add.rn.f32x2 rc, ra, rb;\n\t"
                "mov.b64 {%0, %1}, rc;\n\t}"
                : "=f"(y0), "=f"(y1) : "f"(sv.x), "f"(sv.y), "f"(t1x), "f"(t1y));
            x0 = fmaxf(x0, 0.f); x1 = fmaxf(x1, 0.f);
            y0 = fmaxf(y0, 0.f); y1 = fmaxf(y1, 0.f);
            // acc += a * x  (packed fma, scalar a broadcast to both lanes)
            asm("{\n\t.reg .b64 ra, rx, rc;\n\t"
                "mov.b64 ra, {%4, %4};\n\t"
                "mov.b64 rx, {%2, %3};\n\t"
                "mov.b64 rc, {%0, %1};\n\t"
                "fma.rn.f32x2 rc, ra, rx, rc;\n\t"
                "mov.b64 {%0, %1}, rc;\n\t}"
                : "+f"(a0x), "+f"(a0y) : "f"(x0), "f"(x1), "f"(aA));
            asm("{\n\t.reg .b64 ra, rx, rc;\n\t"
                "mov.b64 ra, {%4, %4};\n\t"
                "mov.b64 rx, {%2, %3};\n\t"
                "mov.b64 rc, {%0, %1};\n\t"
                "fma.rn.f32x2 rc, ra, rx, rc;\n\t"
                "mov.b64 {%0, %1}, rc;\n\t}"
                : "+f"(a1x), "+f"(a1y) : "f"(y0), "f"(y1), "f"(aB));
        }
        __syncthreads();
    }

    // stash v in shared
    {
        float2 v0; v0.x = a0x; v0.y = a0y;
        float2 v1; v1.x = a1x; v1.y = a1y;
        *(float2*)&sh_v[ig * 2 + 0][kp * 2] = v0;
        *(float2*)&sh_v[ig * 2 + 1][kp * 2] = v1;
    }
    __syncthreads();

    // fused epilogue: out = ES + v @ W2 + b2   (softmax rows sum to 1 -> b2 direct)
    int m = tid & 127;
    int g = tid >> 7;                // 0..1, each handles 4 i's
    float o0 = 0.f, o1 = 0.f, o2 = 0.f, o3 = 0.f;
    #pragma unroll 4
    for (int kk = 0; kk < DD; kk++) {
        float w = W2[kk * DD + m];
        o0 += sh_v[g * 4 + 0][kk] * w;
        o1 += sh_v[g * 4 + 1][kk] * w;
        o2 += sh_v[g * 4 + 2][kk] * w;
        o3 += sh_v[g * 4 + 3][kk] * w;
    }
    float bb = b2[m];
    {
        int i = i0 + g * 4;
        size_t base = ((size_t)(b * NN + i)) * DD + m;
        out[base + 0 * DD] = ES[base + 0 * DD] + o0 + bb;
        out[base + 1 * DD] = ES[base + 1 * DD] + o1 + bb;
        out[base + 2 * DD] = ES[base + 2 * DD] + o2 + bb;
        out[base + 3 * DD] = ES[base + 3 * DD] + o3 + bb;
    }
}

// ---------------- launch -------------------------------------------------------------
extern "C" void kernel_launch(void* const* d_in, const int* in_sizes, int n_in,
                              void* d_out, int out_size)
{
    const float* ES  = (const float*)d_in[0];   // (B,N,D)
    const float* Wp  = (const float*)d_in[1];   // (D,D)
    const float* bp  = (const float*)d_in[2];   // (D,)
    const float* EL  = (const float*)d_in[3];   // (N,N)
    const float* W1  = (const float*)d_in[4];   // (2D,D)
    const float* b1  = (const float*)d_in[5];   // (D,)
    const float* W2  = (const float*)d_in[6];   // (D,D)
    const float* b2  = (const float*)d_in[7];   // (D,)
    const float* UN  = (const float*)d_in[8];   // (N,N)

    float* out_state = (float*)d_out;                     // B*N*D
    float* out_A     = (float*)d_out + (size_t)BB * NN * DD;  // B*N*N

    k_combine<<<DD + 1, DD>>>(Wp, W1, bp, b1);
    k_softmax<<<NN, NN>>>(EL, UN, out_A);
    k_proj<<<(BB * NN) / RT, DD>>>(ES);
    k_main<<<dim3(NN / TI, BB), 256>>>(ES, W2, b2, out_state);
}